// round 6
// baseline (speedup 1.0000x reference)
#include <cuda_runtime.h>
#include <cstdint>

// GraphProjection: out[p] = concat(coord[p], bilerp(feat1..feat4))
// h = 250*(-Y)/(-Z)+112, w = 250*X/(-Z)+112, clip [0,223];
// level S in {56,28,14,7}: bilinear at (h,w)/(224/S), JAX index clamping.
//
// R4: coalesced scalar everything -> 90.1us, issue 51.6%, L1 76%.
// R5: 2pt/warp ILP -> neutral (92.5us) => throughput-bound on LSU insts,
//     not latency. 151 mem insts/pt * 1.82cyc ~= measured duration.
// R6: LDG.128 loads (120->30 insts, same 120 wavefronts) + 4-SHFL register
//     transpose so stores remain scalar-coalesced. No smem (preserves L1
//     residency of feat maps), no extra L1 port traffic.

static constexpr int OUT_COLS = 963;

__device__ __forceinline__ float pick4(float a, float b, float c, float d, int m) {
    return (m == 0) ? a : (m == 1) ? b : (m == 2) ? c : d;
}

struct Corners {
    const float* Q11;
    const float* Q21;
    const float* Q12;
    const float* Q22;
    float w11, w21, w12, w22;
};

template <int C, int S>
__device__ __forceinline__ Corners prep(const float* __restrict__ feat,
                                        float x, float y) {
    float x1f = floorf(x), x2f = ceilf(x);
    float y1f = floorf(y), y2f = ceilf(y);
    int xi1 = (int)x1f, xi2 = (int)x2f, yi1 = (int)y1f, yi2 = (int)y2f;
    if (xi1 < 0) xi1 = 0;
    if (yi1 < 0) yi1 = 0;
    if (xi2 < 0) xi2 = 0;
    if (yi2 < 0) yi2 = 0;
    if (xi1 > S - 1) xi1 = S - 1;
    if (yi1 > S - 1) yi1 = S - 1;
    if (xi2 > S - 1) xi2 = S - 1;
    if (yi2 > S - 1) yi2 = S - 1;
    Corners ctx;
    ctx.w11 = (x2f - x) * (y2f - y);
    ctx.w21 = (x - x1f) * (y2f - y);
    ctx.w12 = (x2f - x) * (y - y1f);
    ctx.w22 = (x - x1f) * (y - y1f);
    ctx.Q11 = feat + (xi1 * S + yi1) * C;
    ctx.Q21 = feat + (xi2 * S + yi1) * C;
    ctx.Q12 = feat + (xi1 * S + yi2) * C;
    ctx.Q22 = feat + (xi2 * S + yi2) * C;
    return ctx;
}

// Scalar path (level 1, C=64): coalesced LDG.32/STG.32.
template <int C, int S>
__device__ __forceinline__ void bilerp_scalar(const float* __restrict__ feat,
                                              float x, float y,
                                              float* __restrict__ o, int lane) {
    Corners t = prep<C, S>(feat, x, y);
#pragma unroll
    for (int i = 0; i < C / 32; ++i) {
        int c = lane + 32 * i;
        float a = __ldg(t.Q11 + c);
        float b = __ldg(t.Q21 + c);
        float cc = __ldg(t.Q12 + c);
        float d = __ldg(t.Q22 + c);
        o[c] = t.w11 * a + t.w21 * b + t.w12 * cc + t.w22 * d;
    }
}

// Vector path (C multiple of 128): LDG.128 per corner, in-lane blend,
// 4-shuffle 32x4 warp transpose, coalesced STG.32.
template <int C, int S>
__device__ __forceinline__ void bilerp_vec(const float* __restrict__ feat,
                                           float x, float y,
                                           float* __restrict__ o, int lane) {
    Corners t = prep<C, S>(feat, x, y);
    int k = lane & 3;        // receiver component class
    int rot = lane >> 3;     // sender pre-rotation (0..3)
    int qbase = lane >> 2;   // 0..7

#pragma unroll
    for (int ch = 0; ch < C; ch += 128) {
        float4 a = __ldg((const float4*)(t.Q11 + ch) + lane);
        float4 b = __ldg((const float4*)(t.Q21 + ch) + lane);
        float4 c = __ldg((const float4*)(t.Q12 + ch) + lane);
        float4 d = __ldg((const float4*)(t.Q22 + ch) + lane);
        float rx = t.w11 * a.x + t.w21 * b.x + t.w12 * c.x + t.w22 * d.x;
        float ry = t.w11 * a.y + t.w21 * b.y + t.w12 * c.y + t.w22 * d.y;
        float rz = t.w11 * a.z + t.w21 * b.z + t.w12 * c.z + t.w22 * d.z;
        float rw = t.w11 * a.w + t.w21 * b.w + t.w12 * c.w + t.w22 * d.w;
        // lane holds channels ch+4*lane .. +3 in (rx,ry,rz,rw)

        // sender pre-rotation: u_t = rr[(t + rot) & 3]
        float u0 = pick4(rx, ry, rz, rw, rot);
        float u1 = pick4(ry, rz, rw, rx, rot);
        float u2 = pick4(rz, rw, rx, ry, rot);
        float u3 = pick4(rw, rx, ry, rz, rot);

        // round t: fetch from src = qbase + 8*((k - t) & 3)
        float v0 = __shfl_sync(0xffffffffu, u0, qbase + 8 * (k & 3));
        float v1 = __shfl_sync(0xffffffffu, u1, qbase + 8 * ((k - 1) & 3));
        float v2 = __shfl_sync(0xffffffffu, u2, qbase + 8 * ((k - 2) & 3));
        float v3 = __shfl_sync(0xffffffffu, u3, qbase + 8 * ((k - 3) & 3));

        // s_j = v_{(k - j) & 3}  (channel ch + lane + 32*j)
        float s0 = pick4(v0, v1, v2, v3, k);
        float s1 = pick4(v3, v0, v1, v2, k);
        float s2 = pick4(v2, v3, v0, v1, k);
        float s3 = pick4(v1, v2, v3, v0, k);

        o[ch + lane +  0] = s0;
        o[ch + lane + 32] = s1;
        o[ch + lane + 64] = s2;
        o[ch + lane + 96] = s3;
    }
}

__global__ void __launch_bounds__(256)
graph_projection_kernel(const float* __restrict__ coord,
                        const float* __restrict__ f1,
                        const float* __restrict__ f2,
                        const float* __restrict__ f3,
                        const float* __restrict__ f4,
                        float* __restrict__ out, int N) {
    int p = (blockIdx.x * blockDim.x + threadIdx.x) >> 5;  // warp = point
    int lane = threadIdx.x & 31;
    if (p >= N) return;

    float X = __ldg(coord + 3 * p + 0);
    float Y = __ldg(coord + 3 * p + 1);
    float Z = __ldg(coord + 3 * p + 2);

    float h = 250.0f * (-Y) / (-Z) + 112.0f;
    float w = 250.0f * X / (-Z) + 112.0f;
    h = (h < 0.0f) ? 0.0f : ((h > 223.0f) ? 223.0f : h);
    w = (w < 0.0f) ? 0.0f : ((w > 223.0f) ? 223.0f : w);

    float* __restrict__ orow = out + (size_t)p * OUT_COLS;
    if (lane == 0) orow[0] = X;
    if (lane == 1) orow[1] = Y;
    if (lane == 2) orow[2] = Z;

    // scales: 224/56=4, 224/28=8, 224/14=16, 224/7=32 (exact pow2)
    bilerp_scalar<64, 56>(f1, h * 0.25f,    w * 0.25f,    orow + 3,   lane);
    bilerp_vec<128, 28>(f2, h * 0.125f,   w * 0.125f,   orow + 67,  lane);
    bilerp_vec<256, 14>(f3, h * 0.0625f,  w * 0.0625f,  orow + 195, lane);
    bilerp_vec<512, 7>(f4, h * 0.03125f,  w * 0.03125f, orow + 451, lane);
}

extern "C" void kernel_launch(void* const* d_in, const int* in_sizes, int n_in,
                              void* d_out, int out_size) {
    const float* coord = (const float*)d_in[0];
    const float* f1 = (const float*)d_in[1];
    const float* f2 = (const float*)d_in[2];
    const float* f3 = (const float*)d_in[3];
    const float* f4 = (const float*)d_in[4];
    float* out = (float*)d_out;

    int N = in_sizes[0] / 3;

    int blocks = (N + 7) / 8;  // 8 warps/block, 1 point/warp
    graph_projection_kernel<<<blocks, 256>>>(coord, f1, f2, f3, f4, out, N);
}